// round 6
// baseline (speedup 1.0000x reference)
#include <cuda_runtime.h>

// Fused: out[b,v] = sum_c x[b,c,v] * coef[b][c] + bias[b]
//   coef[b][c] = conv_w[c] + w[b]*scale[b], bias[b] = conv_b + shift[b]
//   s = silu(z_prjs[b]); w = s.hwd_w + hwd_b; scale = s.c_w[0]+c_b[0]; shift = s.c_w[1]+c_b[1]
// Single kernel; 4 float4 per thread with a 128-reg budget for deep LDG batching.

#define BATCH 8
#define CH    16
#define SPATIAL (96*96*96)          // 884736 floats per (b,c) plane
#define N4    (SPATIAL/4)           // 221184 float4 per plane
#define TPB   256
#define V4_PER_THREAD 4
#define BLOCKS_PER_B (N4 / (TPB * V4_PER_THREAD))   // 216, exact

__device__ __forceinline__ float silu_f(float v) {
    return v / (1.0f + __expf(-v));
}

__global__ __launch_bounds__(TPB, 2) void fused_kernel(
    const float* __restrict__ x,        // [B, C, SPATIAL]
    const float* __restrict__ z_prjs,   // [B,5]
    const float* __restrict__ conv_w,   // [1,16]
    const float* __restrict__ conv_b,   // [1]
    const float* __restrict__ hwd_w,    // [1,5]
    const float* __restrict__ hwd_b,    // [1]
    const float* __restrict__ c_w,      // [2,5]
    const float* __restrict__ c_b,      // [2]
    float* __restrict__ out)            // [B, 1, SPATIAL]
{
    const int b = blockIdx.y;

    __shared__ float sc[CH + 1];

    // Threads 0..16 redundantly compute the per-batch scalars (tiny; L2-hit).
    if (threadIdx.x <= CH) {
        float s0 = silu_f(z_prjs[b * 5 + 0]);
        float s1 = silu_f(z_prjs[b * 5 + 1]);
        float s2 = silu_f(z_prjs[b * 5 + 2]);
        float s3 = silu_f(z_prjs[b * 5 + 3]);
        float s4 = silu_f(z_prjs[b * 5 + 4]);

        if (threadIdx.x < CH) {
            float w  = hwd_b[0] + s0*hwd_w[0] + s1*hwd_w[1] + s2*hwd_w[2]
                                 + s3*hwd_w[3] + s4*hwd_w[4];
            float sl = c_b[0]   + s0*c_w[0]   + s1*c_w[1]   + s2*c_w[2]
                                 + s3*c_w[3]   + s4*c_w[4];
            sc[threadIdx.x] = conv_w[threadIdx.x] + w * sl;
        } else {
            float sh = c_b[1]   + s0*c_w[5]   + s1*c_w[6]   + s2*c_w[7]
                                 + s3*c_w[8]   + s4*c_w[9];
            sc[CH] = conv_b[0] + sh;
        }
    }
    __syncthreads();

    const int idx = blockIdx.x * (TPB * V4_PER_THREAD) + threadIdx.x;
    const float4* __restrict__ x4 =
        reinterpret_cast<const float4*>(x) + (size_t)b * CH * N4 + idx;

    const float bias = sc[CH];
    float4 acc0 = make_float4(bias, bias, bias, bias);
    float4 acc1 = acc0, acc2 = acc0, acc3 = acc0;

    #pragma unroll
    for (int c = 0; c < CH; c++) {
        const float4* p = x4 + (size_t)c * N4;
        float4 a0 = p[0];
        float4 a1 = p[TPB];
        float4 a2 = p[2 * TPB];
        float4 a3 = p[3 * TPB];
        float k = sc[c];
        acc0.x += a0.x * k; acc0.y += a0.y * k; acc0.z += a0.z * k; acc0.w += a0.w * k;
        acc1.x += a1.x * k; acc1.y += a1.y * k; acc1.z += a1.z * k; acc1.w += a1.w * k;
        acc2.x += a2.x * k; acc2.y += a2.y * k; acc2.z += a2.z * k; acc2.w += a2.w * k;
        acc3.x += a3.x * k; acc3.y += a3.y * k; acc3.z += a3.z * k; acc3.w += a3.w * k;
    }

    float4* o = reinterpret_cast<float4*>(out) + (size_t)b * N4 + idx;
    o[0]       = acc0;
    o[TPB]     = acc1;
    o[2 * TPB] = acc2;
    o[3 * TPB] = acc3;
}

extern "C" void kernel_launch(void* const* d_in, const int* in_sizes, int n_in,
                              void* d_out, int out_size)
{
    const float* x      = (const float*)d_in[0];
    const float* z_prjs = (const float*)d_in[1];
    const float* conv_w = (const float*)d_in[2];
    const float* conv_b = (const float*)d_in[3];
    const float* hwd_w  = (const float*)d_in[4];
    const float* hwd_b  = (const float*)d_in[5];
    const float* c_w    = (const float*)d_in[6];
    const float* c_b    = (const float*)d_in[7];
    float* out = (float*)d_out;

    dim3 grid(BLOCKS_PER_B, BATCH);
    fused_kernel<<<grid, TPB>>>(x, z_prjs, conv_w, conv_b, hwd_w, hwd_b,
                                c_w, c_b, out);
}

// round 8
// speedup vs baseline: 1.0229x; 1.0229x over previous
#include <cuda_runtime.h>

// Fused: out[b,v] = sum_c x[b,c,v] * coef[b][c] + bias[b]
//   coef[b][c] = conv_w[c] + w[b]*scale[b], bias[b] = conv_b + shift[b]
//   s = silu(z_prjs[b]); w = s.hwd_w + hwd_b; scale = s.c_w[0]+c_b[0]; shift = s.c_w[1]+c_b[1]
// Single kernel; 2 float4 per thread (best measured config) + streaming
// cache hints (__ldcs/__stcs) since the pass has zero reuse.

#define BATCH 8
#define CH    16
#define SPATIAL (96*96*96)          // 884736 floats per (b,c) plane
#define N4    (SPATIAL/4)           // 221184 float4 per plane
#define TPB   256
#define V4_PER_THREAD 2
#define BLOCKS_PER_B (N4 / (TPB * V4_PER_THREAD))   // 432, exact

__device__ __forceinline__ float silu_f(float v) {
    return v / (1.0f + __expf(-v));
}

__global__ __launch_bounds__(TPB, 4) void fused_kernel(
    const float* __restrict__ x,        // [B, C, SPATIAL]
    const float* __restrict__ z_prjs,   // [B,5]
    const float* __restrict__ conv_w,   // [1,16]
    const float* __restrict__ conv_b,   // [1]
    const float* __restrict__ hwd_w,    // [1,5]
    const float* __restrict__ hwd_b,    // [1]
    const float* __restrict__ c_w,      // [2,5]
    const float* __restrict__ c_b,      // [2]
    float* __restrict__ out)            // [B, 1, SPATIAL]
{
    const int b = blockIdx.y;

    __shared__ float sc[CH + 1];

    // Threads 0..16 redundantly compute the per-batch scalars (tiny; L2-hit).
    if (threadIdx.x <= CH) {
        float s0 = silu_f(z_prjs[b * 5 + 0]);
        float s1 = silu_f(z_prjs[b * 5 + 1]);
        float s2 = silu_f(z_prjs[b * 5 + 2]);
        float s3 = silu_f(z_prjs[b * 5 + 3]);
        float s4 = silu_f(z_prjs[b * 5 + 4]);

        if (threadIdx.x < CH) {
            float w  = hwd_b[0] + s0*hwd_w[0] + s1*hwd_w[1] + s2*hwd_w[2]
                                 + s3*hwd_w[3] + s4*hwd_w[4];
            float sl = c_b[0]   + s0*c_w[0]   + s1*c_w[1]   + s2*c_w[2]
                                 + s3*c_w[3]   + s4*c_w[4];
            sc[threadIdx.x] = conv_w[threadIdx.x] + w * sl;
        } else {
            float sh = c_b[1]   + s0*c_w[5]   + s1*c_w[6]   + s2*c_w[7]
                                 + s3*c_w[8]   + s4*c_w[9];
            sc[CH] = conv_b[0] + sh;
        }
    }
    __syncthreads();

    const int idx = blockIdx.x * (TPB * V4_PER_THREAD) + threadIdx.x;
    const float4* __restrict__ x4 =
        reinterpret_cast<const float4*>(x) + (size_t)b * CH * N4 + idx;

    const float bias = sc[CH];
    float4 acc0 = make_float4(bias, bias, bias, bias);
    float4 acc1 = acc0;

    #pragma unroll
    for (int c = 0; c < CH; c++) {
        const float4* p = x4 + (size_t)c * N4;
        float4 a  = __ldcs(p);          // streaming (evict-first) load
        float4 bb = __ldcs(p + TPB);
        float k = sc[c];
        acc0.x += a.x * k;  acc0.y += a.y * k;
        acc0.z += a.z * k;  acc0.w += a.w * k;
        acc1.x += bb.x * k; acc1.y += bb.y * k;
        acc1.z += bb.z * k; acc1.w += bb.w * k;
    }

    float4* o = reinterpret_cast<float4*>(out) + (size_t)b * N4 + idx;
    __stcs(o,       acc0);              // streaming store
    __stcs(o + TPB, acc1);
}

extern "C" void kernel_launch(void* const* d_in, const int* in_sizes, int n_in,
                              void* d_out, int out_size)
{
    const float* x      = (const float*)d_in[0];
    const float* z_prjs = (const float*)d_in[1];
    const float* conv_w = (const float*)d_in[2];
    const float* conv_b = (const float*)d_in[3];
    const float* hwd_w  = (const float*)d_in[4];
    const float* hwd_b  = (const float*)d_in[5];
    const float* c_w    = (const float*)d_in[6];
    const float* c_b    = (const float*)d_in[7];
    float* out = (float*)d_out;

    dim3 grid(BLOCKS_PER_B, BATCH);
    fused_kernel<<<grid, TPB>>>(x, z_prjs, conv_w, conv_b, hwd_w, hwd_b,
                                c_w, c_b, out);
}

// round 9
// speedup vs baseline: 1.0282x; 1.0052x over previous
#include <cuda_runtime.h>

// Fused: out[b,v] = sum_c x[b,c,v] * coef[b][c] + bias[b]
//   coef[b][c] = conv_w[c] + w[b]*scale[b], bias[b] = conv_b + shift[b]
//   s = silu(z_prjs[b]); w = s.hwd_w + hwd_b; scale = s.c_w[0]+c_b[0]; shift = s.c_w[1]+c_b[1]
// Single kernel; 2 float4 per thread, __ldcs streaming loads,
// __stwt write-through stores (output bypasses L2 allocation).

#define BATCH 8
#define CH    16
#define SPATIAL (96*96*96)          // 884736 floats per (b,c) plane
#define N4    (SPATIAL/4)           // 221184 float4 per plane
#define TPB   256
#define V4_PER_THREAD 2
#define BLOCKS_PER_B (N4 / (TPB * V4_PER_THREAD))   // 432, exact

__device__ __forceinline__ float silu_f(float v) {
    return v / (1.0f + __expf(-v));
}

__global__ __launch_bounds__(TPB, 4) void fused_kernel(
    const float* __restrict__ x,        // [B, C, SPATIAL]
    const float* __restrict__ z_prjs,   // [B,5]
    const float* __restrict__ conv_w,   // [1,16]
    const float* __restrict__ conv_b,   // [1]
    const float* __restrict__ hwd_w,    // [1,5]
    const float* __restrict__ hwd_b,    // [1]
    const float* __restrict__ c_w,      // [2,5]
    const float* __restrict__ c_b,      // [2]
    float* __restrict__ out)            // [B, 1, SPATIAL]
{
    const int b = blockIdx.y;

    __shared__ float sc[CH + 1];

    // Threads 0..16 redundantly compute the per-batch scalars (tiny; L2-hit).
    if (threadIdx.x <= CH) {
        float s0 = silu_f(z_prjs[b * 5 + 0]);
        float s1 = silu_f(z_prjs[b * 5 + 1]);
        float s2 = silu_f(z_prjs[b * 5 + 2]);
        float s3 = silu_f(z_prjs[b * 5 + 3]);
        float s4 = silu_f(z_prjs[b * 5 + 4]);

        if (threadIdx.x < CH) {
            float w  = hwd_b[0] + s0*hwd_w[0] + s1*hwd_w[1] + s2*hwd_w[2]
                                 + s3*hwd_w[3] + s4*hwd_w[4];
            float sl = c_b[0]   + s0*c_w[0]   + s1*c_w[1]   + s2*c_w[2]
                                 + s3*c_w[3]   + s4*c_w[4];
            sc[threadIdx.x] = conv_w[threadIdx.x] + w * sl;
        } else {
            float sh = c_b[1]   + s0*c_w[5]   + s1*c_w[6]   + s2*c_w[7]
                                 + s3*c_w[8]   + s4*c_w[9];
            sc[CH] = conv_b[0] + sh;
        }
    }
    __syncthreads();

    const int idx = blockIdx.x * (TPB * V4_PER_THREAD) + threadIdx.x;
    const float4* __restrict__ x4 =
        reinterpret_cast<const float4*>(x) + (size_t)b * CH * N4 + idx;

    const float bias = sc[CH];
    float4 acc0 = make_float4(bias, bias, bias, bias);
    float4 acc1 = acc0;

    #pragma unroll
    for (int c = 0; c < CH; c++) {
        const float4* p = x4 + (size_t)c * N4;
        float4 a  = __ldcs(p);          // streaming (evict-first) load
        float4 bb = __ldcs(p + TPB);
        float k = sc[c];
        acc0.x += a.x * k;  acc0.y += a.y * k;
        acc0.z += a.z * k;  acc0.w += a.w * k;
        acc1.x += bb.x * k; acc1.y += bb.y * k;
        acc1.z += bb.z * k; acc1.w += bb.w * k;
    }

    float4* o = reinterpret_cast<float4*>(out) + (size_t)b * N4 + idx;
    __stwt(o,       acc0);              // write-through store (no L2 dirty lines)
    __stwt(o + TPB, acc1);
}

extern "C" void kernel_launch(void* const* d_in, const int* in_sizes, int n_in,
                              void* d_out, int out_size)
{
    const float* x      = (const float*)d_in[0];
    const float* z_prjs = (const float*)d_in[1];
    const float* conv_w = (const float*)d_in[2];
    const float* conv_b = (const float*)d_in[3];
    const float* hwd_w  = (const float*)d_in[4];
    const float* hwd_b  = (const float*)d_in[5];
    const float* c_w    = (const float*)d_in[6];
    const float* c_b    = (const float*)d_in[7];
    float* out = (float*)d_out;

    dim3 grid(BLOCKS_PER_B, BATCH);
    fused_kernel<<<grid, TPB>>>(x, z_prjs, conv_w, conv_b, hwd_w, hwd_b,
                                c_w, c_b, out);
}